// round 14
// baseline (speedup 1.0000x reference)
#include <cuda_runtime.h>
#include <cuda_fp16.h>
#include <cstdint>

// Problem constants (B,H,W,D = 32,32,32,64; K = 1024)
#define N_ROWS 32768
#define DIM    64
#define KCODES 1024
#define M_TILE 128
#define N_TILE 128
#define KSTORE 128              // stored halfs per row: [hi(64) | mid(64)]
#define KSTEPS 12               // logical K = 192 via hi-region reuse
#define NT     512              // threads per CTA in main kernel (16 warps, 4x4)

// ---------------------------------------------------------------------------
// Device scratch (no allocation allowed)
// ---------------------------------------------------------------------------
__device__ unsigned long long g_rowbest[N_ROWS];   // (dist_bits<<32)|code
__device__ unsigned int       g_colmin[KCODES];    // per-code min dist (float bits)
__device__ float              g_xnorm[N_ROWS];
__device__ float              g_cnorm[KCODES];
__device__ float              g_partials[N_ROWS / 256];
__device__ unsigned int       g_done;
__device__ __align__(16) __half g_xaug[(size_t)N_ROWS * KSTORE];  // 8.4 MB
__device__ __align__(16) __half g_caug[(size_t)KCODES * KSTORE];  // 256 KB

// ---------------------------------------------------------------------------
// SMEM layout (dynamic). Row stride: 128 halfs = 256 B + 16 B pad = 272 B
// (272/4 = 68 ≡ 4 mod 32 banks => same conflict-free ldmatrix pattern as before).
// ---------------------------------------------------------------------------
#define ROWB      272
#define SO_CN     0                        // 128 floats
#define SO_XN     512                      // 128 floats
#define SO_ROWRED 1024                     // 128 u64
#define SO_COLRED 2048                     // 128 u32
#define SO_A      2560                     // 128 * 272 B = 34816
#define SO_B      (SO_A + M_TILE * ROWB)   // 37376
#define SMEM_SZ   (SO_B + N_TILE * ROWB)   // 72192 B

// k-step -> byte offset within a 256 B row ([hi @0, mid @128]); constants fold.
//   ks 0-3 : hi_x  * hi_c      ks 4-7 : hi_x * mid_c     ks 8-11: mid_x * hi_c
#define AOFF(ks) (((ks) < 8) ? (((ks) & 3) * 32) : (128 + ((ks) & 3) * 32))
#define BOFF(ks) (((ks) < 4) ? ((ks) * 32) : ((ks) < 8) ? (128 + ((ks) & 3) * 32) \
                                           : (((ks) & 3) * 32))

__device__ __forceinline__ uint32_t smem_to_u32(const void* p) {
    uint32_t a;
    asm("{ .reg .u64 t; cvta.to.shared.u64 t, %1; cvt.u32.u64 %0, t; }"
        : "=r"(a) : "l"(p));
    return a;
}

#define LDSM_X4(r0, r1, r2, r3, addr) \
    asm volatile("ldmatrix.sync.aligned.m8n8.x4.shared.b16 {%0,%1,%2,%3}, [%4];" \
                 : "=r"(r0), "=r"(r1), "=r"(r2), "=r"(r3) : "r"(addr))

#define MMA16816(c, a0, a1, a2, a3, b0, b1) \
    asm volatile( \
        "mma.sync.aligned.m16n8k16.row.col.f32.f16.f16.f32 " \
        "{%0,%1,%2,%3}, {%4,%5,%6,%7}, {%8,%9}, {%0,%1,%2,%3};" \
        : "+f"((c)[0]), "+f"((c)[1]), "+f"((c)[2]), "+f"((c)[3]) \
        : "r"(a0), "r"(a1), "r"(a2), "r"(a3), "r"(b0), "r"(b1))

#define CP_ASYNC16(dst, src) \
    asm volatile("cp.async.ca.shared.global [%0], [%1], 16;" \
                 :: "r"((uint32_t)(dst)), "l"(src))
#define CP_ASYNC_COMMIT() asm volatile("cp.async.commit_group;" ::: "memory")
#define CP_ASYNC_WAIT0()  asm volatile("cp.async.wait_group 0;" ::: "memory")

// ---------------------------------------------------------------------------
// fp16 2-level split: x = hi + mid (+eps). Stored layout per row: [hi64 | mid64].
// Products taken: hi*hi, hi*mid, mid*hi (drop mid*mid ~ 2^-22 relative).
// ---------------------------------------------------------------------------
__device__ __forceinline__ void split2h(float v, __half& h, __half& m) {
    h = __float2half_rn(v);
    m = __float2half_rn(v - __half2float(h));
}
__device__ __forceinline__ uint32_t hpack(__half a, __half b) {
    __half2 t = __halves2half2(a, b);
    return *reinterpret_cast<uint32_t*>(&t);
}

// ---------------------------------------------------------------------------
// Kernel 1: norms + scratch init + fp16 split. 16 threads per row (one per
// float4 quad), coalesced reads and writes, 16-lane shuffle for norms.
// ---------------------------------------------------------------------------
__global__ void vq_prep_split(const float* __restrict__ x,
                              const float* __restrict__ cb) {
    int t = blockIdx.x * blockDim.x + threadIdx.x;  // (N_ROWS+KCODES)*16 threads
    if (t == 0) g_done = 0;
    int rowg = t >> 4, q = t & 15;
    const bool isx = rowg < N_ROWS;
    const int row = isx ? rowg : rowg - N_ROWS;
    float4 v = reinterpret_cast<const float4*>(isx ? x : cb)[(size_t)row * 16 + q];

    float s = v.x * v.x + v.y * v.y + v.z * v.z + v.w * v.w;
#pragma unroll
    for (int off = 1; off <= 8; off <<= 1)
        s += __shfl_xor_sync(0xFFFFFFFFu, s, off);

    __half h[4], m[4];
    split2h(v.x, h[0], m[0]);
    split2h(v.y, h[1], m[1]);
    split2h(v.z, h[2], m[2]);
    split2h(v.w, h[3], m[3]);
    uint2 hh = make_uint2(hpack(h[0], h[1]), hpack(h[2], h[3]));
    uint2 mm = make_uint2(hpack(m[0], m[1]), hpack(m[2], m[3]));
    __half* aug = isx ? g_xaug : g_caug;
    size_t base = (size_t)row * KSTORE + q * 4;
    *reinterpret_cast<uint2*>(&aug[base + 0]) = hh;        // hi region [0,64)
    *reinterpret_cast<uint2*>(&aug[base + 64]) = mm;       // mid region [64,128)
    if (q == 0) {
        if (isx) {
            g_xnorm[row] = s;
            g_rowbest[row] = 0xFFFFFFFFFFFFFFFFull;
        } else {
            g_cnorm[row] = s;
            g_colmin[row] = 0x7F800000u;
        }
    }
}

// ---------------------------------------------------------------------------
// Kernel 2: mma.sync HMMA GEMM tile (128x128, logical K=192 from 128 stored)
// 16 warps in a 4x4 grid; warp tile 32x32; cp.async staging; hi-region reuse.
// ---------------------------------------------------------------------------
__global__ void __launch_bounds__(NT, 2) vq_main_mma() {
    extern __shared__ char smem[];
    uint32_t sb = smem_to_u32(smem);
    float* cn_s = reinterpret_cast<float*>(smem + SO_CN);
    float* xn_s = reinterpret_cast<float*>(smem + SO_XN);
    unsigned long long* rowred =
        reinterpret_cast<unsigned long long*>(smem + SO_ROWRED);
    unsigned int* colred = reinterpret_cast<unsigned int*>(smem + SO_COLRED);

    const int tid = threadIdx.x;
    const int wid = tid >> 5, lane = tid & 31;
    const int wm = wid & 3;       // m block of 32
    const int wn = wid >> 2;      // n block of 32
    const int m0 = blockIdx.x * M_TILE;
    const int c0 = blockIdx.y * N_TILE;

    // Stage A and B tiles (128 x 128 halfs each) via cp.async.
    const uint4* xa = reinterpret_cast<const uint4*>(g_xaug);  // 16 uint4 / row
    const uint4* ca = reinterpret_cast<const uint4*>(g_caug);
#pragma unroll
    for (int i = 0; i < 4; i++) {
        int idx = tid + i * NT;             // 0..2047
        int r = idx >> 4, q = idx & 15;
        CP_ASYNC16(sb + SO_A + r * ROWB + q * 16, &xa[(size_t)(m0 + r) * 16 + q]);
        CP_ASYNC16(sb + SO_B + r * ROWB + q * 16, &ca[(size_t)(c0 + r) * 16 + q]);
    }
    CP_ASYNC_COMMIT();

    if (tid < 128) {
        cn_s[tid] = g_cnorm[c0 + tid];
        xn_s[tid] = g_xnorm[m0 + tid];
        rowred[tid] = 0xFFFFFFFFFFFFFFFFull;
        colred[tid] = 0x7F800000u;
    }
    CP_ASYNC_WAIT0();
    __syncthreads();

    // ldmatrix bases
    // A x4: lanes 0-15 -> rows (lane&15) @k0, lanes 16-31 -> same rows @k+8
    uint32_t a_base = sb + SO_A + (wm * 32 + (lane & 15)) * ROWB + (lane >> 4) * 16;
    // B x4: group g = lane>>3: g0 n0-7@k0, g1 n0-7@k8, g2 n8-15@k0, g3 n8-15@k8
    const int bg = lane >> 3;
    const int bn = ((bg >> 1) << 3) + (lane & 7);
    const int bk = (bg & 1) * 16;
    uint32_t b_base0 = sb + SO_B + (wn * 32 + 0 + bn) * ROWB + bk;
    uint32_t b_base1 = sb + SO_B + (wn * 32 + 16 + bn) * ROWB + bk;

    float acc[2][4][4];
#pragma unroll
    for (int mi = 0; mi < 2; mi++)
#pragma unroll
        for (int ni = 0; ni < 4; ni++)
#pragma unroll
            for (int j = 0; j < 4; j++) acc[mi][ni][j] = 0.f;

#pragma unroll
    for (int ks = 0; ks < KSTEPS; ks++) {
        const int ao = AOFF(ks), bo = BOFF(ks);
        uint32_t a[2][4], b[2][4];
#pragma unroll
        for (int mi = 0; mi < 2; mi++)
            LDSM_X4(a[mi][0], a[mi][1], a[mi][2], a[mi][3],
                    a_base + mi * 16 * ROWB + ao);
        LDSM_X4(b[0][0], b[0][1], b[0][2], b[0][3], b_base0 + bo);
        LDSM_X4(b[1][0], b[1][1], b[1][2], b[1][3], b_base1 + bo);
#pragma unroll
        for (int mi = 0; mi < 2; mi++) {
#pragma unroll
            for (int ni = 0; ni < 4; ni++) {
                const int p = ni >> 1, o = (ni & 1) * 2;
                MMA16816(acc[mi][ni], a[mi][0], a[mi][1], a[mi][2], a[mi][3],
                         b[p][o], b[p][o + 1]);
            }
        }
    }

    // ---------------- Epilogue ----------------
    const int qr = lane >> 2, qc = lane & 3;
    const float INF = __int_as_float(0x7f800000);
    float cmin[4][2];
#pragma unroll
    for (int ni = 0; ni < 4; ni++) { cmin[ni][0] = INF; cmin[ni][1] = INF; }

#pragma unroll
    for (int mi = 0; mi < 2; mi++) {
#pragma unroll
        for (int h = 0; h < 2; h++) {
            int row_l = wm * 32 + mi * 16 + qr + 8 * h;
            float xn = xn_s[row_l];
            float bd = INF;
            int bc = 0;
#pragma unroll
            for (int ni = 0; ni < 4; ni++) {
#pragma unroll
                for (int c = 0; c < 2; c++) {
                    int col_l = wn * 32 + ni * 8 + 2 * qc + c;
                    float d = fmaf(-2.f, acc[mi][ni][2 * h + c], xn + cn_s[col_l]);
                    if (d < bd) { bd = d; bc = col_l; }
                    cmin[ni][c] = fminf(cmin[ni][c], d);
                }
            }
            unsigned long long u =
                ((unsigned long long)__float_as_uint(bd) << 32) |
                (unsigned int)(c0 + bc);
#pragma unroll
            for (int off = 1; off <= 2; off <<= 1) {
                unsigned long long o = __shfl_xor_sync(0xFFFFFFFFu, u, off);
                if (o < u) u = o;
            }
            if (qc == 0) atomicMin(&rowred[row_l], u);
        }
    }
#pragma unroll
    for (int ni = 0; ni < 4; ni++) {
#pragma unroll
        for (int c = 0; c < 2; c++) {
            float v = cmin[ni][c];
#pragma unroll
            for (int off = 4; off <= 16; off <<= 1)
                v = fminf(v, __shfl_xor_sync(0xFFFFFFFFu, v, off));
            if (qr == 0) {
                int col_l = wn * 32 + ni * 8 + 2 * qc + c;
                atomicMin(&colred[col_l], __float_as_uint(v));
            }
        }
    }
    __syncthreads();
    if (tid < 128) {
        atomicMin(&g_rowbest[m0 + tid], rowred[tid]);
        atomicMin(&g_colmin[c0 + tid], colred[tid]);
    }
}

// ---------------------------------------------------------------------------
// Kernel 3 (fused): gather emb, write out = x + (emb-x), partial SSE;
// last block finalizes the loss scalar (deterministic fixed-order sums).
// ---------------------------------------------------------------------------
__global__ void vq_gather_final(const float* __restrict__ x,
                                const float* __restrict__ cb,
                                float* __restrict__ out, int nd, int out_size) {
    int row = blockIdx.x * blockDim.x + threadIdx.x;
    int tok = (int)(unsigned int)(g_rowbest[row] & 0xFFFFFFFFull);
    const float4* xg = reinterpret_cast<const float4*>(x) + (size_t)row * 16;
    const float4* cg = reinterpret_cast<const float4*>(cb) + (size_t)tok * 16;
    float4* og = reinterpret_cast<float4*>(out) + (size_t)row * 16;
    float s = 0.f;
#pragma unroll
    for (int i = 0; i < 16; i++) {
        float4 xv = xg[i];
        float4 e = cg[i];
        float dx = e.x - xv.x, dy = e.y - xv.y, dz = e.z - xv.z, dw = e.w - xv.w;
        s += dx * dx + dy * dy + dz * dz + dw * dw;
        og[i] = make_float4(xv.x + dx, xv.y + dy, xv.z + dz, xv.w + dw);
    }
#pragma unroll
    for (int off = 16; off; off >>= 1) s += __shfl_xor_sync(0xFFFFFFFFu, s, off);
    __shared__ float red[8];
    __shared__ unsigned int ticket;
    int lane = threadIdx.x & 31, wid = threadIdx.x >> 5;
    if (lane == 0) red[wid] = s;
    __syncthreads();
    if (threadIdx.x == 0) {
        float t = 0.f;
#pragma unroll
        for (int i = 0; i < 8; i++) t += red[i];
        g_partials[blockIdx.x] = t;
        __threadfence();
        ticket = atomicAdd(&g_done, 1u);
    }
    __syncthreads();
    if (ticket != gridDim.x - 1) return;

    // Last block: finalize the loss (256 threads)
    int t = threadIdx.x;
    float ps = (t < (N_ROWS / 256)) ? g_partials[t] : 0.f;
    float cm = 0.f;
#pragma unroll
    for (int i = 0; i < KCODES / 256; i++)
        cm += __uint_as_float(g_colmin[t + i * 256]);
#pragma unroll
    for (int off = 16; off; off >>= 1) {
        ps += __shfl_xor_sync(0xFFFFFFFFu, ps, off);
        cm += __shfl_xor_sync(0xFFFFFFFFu, cm, off);
    }
    __shared__ float sh_s[8], sh_c[8];
    if (lane == 0) { sh_s[wid] = ps; sh_c[wid] = cm; }
    __syncthreads();
    if (t == 0) {
        float st = 0.f, ct = 0.f;
#pragma unroll
        for (int i = 0; i < 8; i++) { st += sh_s[i]; ct += sh_c[i]; }
        float loss = 1.25f * (st / (float)nd) + 0.1f * (ct * (1.f / (float)KCODES));
        for (int i = nd; i < out_size; i++) out[i] = loss;
    }
}

// ---------------------------------------------------------------------------
extern "C" void kernel_launch(void* const* d_in, const int* in_sizes, int n_in,
                              void* d_out, int out_size) {
    const float* x = (const float*)d_in[0];   // [32,32,32,64] fp32
    const float* cb = (const float*)d_in[1];  // [1024,64] fp32
    float* out = (float*)d_out;
    int nd = in_sizes[0];  // 2097152

    cudaFuncSetAttribute(vq_main_mma, cudaFuncAttributeMaxDynamicSharedMemorySize,
                         SMEM_SZ);

    vq_prep_split<<<((N_ROWS + KCODES) * 16) / 256, 256>>>(x, cb);
    dim3 grid(N_ROWS / M_TILE, KCODES / N_TILE);  // (256, 8)
    vq_main_mma<<<grid, NT, SMEM_SZ>>>();
    vq_gather_final<<<N_ROWS / 256, 256>>>(x, cb, out, nd, out_size);
}

// round 15
// speedup vs baseline: 1.7248x; 1.7248x over previous
#include <cuda_runtime.h>
#include <cuda_fp16.h>
#include <cstdint>

// Problem constants (B,H,W,D = 32,32,32,64; K = 1024)
#define N_ROWS 32768
#define DIM    64
#define KCODES 1024
#define M_TILE 128
#define N_TILE 128
#define CTILES 2                // c-tiles per CTA (A staged once)
#define KAUG   192              // 3 chunks x 64 (fp16 2-level split, 3 product terms)
#define KSTEPS (KAUG / 16)      // 12
#define NT     512              // threads per CTA in main kernel (16 warps, 4x4)

// ---------------------------------------------------------------------------
// Device scratch (no allocation allowed)
// ---------------------------------------------------------------------------
__device__ unsigned long long g_rowbest[N_ROWS];   // (dist_bits<<32)|code
__device__ unsigned int       g_colmin[KCODES];    // per-code min dist (float bits)
__device__ float              g_xnorm[N_ROWS];
__device__ float              g_cnorm[KCODES];
__device__ float              g_partials[N_ROWS / 256];
__device__ unsigned int       g_done;
__device__ __align__(16) __half g_xaug[(size_t)N_ROWS * KAUG];  // 12.6 MB, 384 B rows
__device__ __align__(16) __half g_caug[(size_t)KCODES * KAUG];  // 384 KB

// ---------------------------------------------------------------------------
// SMEM layout (dynamic). Padded K-stride: 192 halfs -> 200 halfs = 400 B
// (rows land on distinct 4-bank groups => conflict-free ldmatrix).
// ---------------------------------------------------------------------------
#define ROWB      400
#define SO_CN     0                        // 128 floats
#define SO_XN     512                      // 128 floats
#define SO_ROWRED 1024                     // 128 u64
#define SO_COLRED 2048                     // 128 u32
#define SO_A      2560                     // 128 * 400 B = 51200
#define SO_B      (SO_A + M_TILE * ROWB)   // 53760
#define SMEM_SZ   (SO_B + N_TILE * ROWB)   // 104960 B

__device__ __forceinline__ uint32_t smem_to_u32(const void* p) {
    uint32_t a;
    asm("{ .reg .u64 t; cvta.to.shared.u64 t, %1; cvt.u32.u64 %0, t; }"
        : "=r"(a) : "l"(p));
    return a;
}

#define LDSM_X4(r0, r1, r2, r3, addr) \
    asm volatile("ldmatrix.sync.aligned.m8n8.x4.shared.b16 {%0,%1,%2,%3}, [%4];" \
                 : "=r"(r0), "=r"(r1), "=r"(r2), "=r"(r3) : "r"(addr))

#define MMA16816(c, a0, a1, a2, a3, b0, b1) \
    asm volatile( \
        "mma.sync.aligned.m16n8k16.row.col.f32.f16.f16.f32 " \
        "{%0,%1,%2,%3}, {%4,%5,%6,%7}, {%8,%9}, {%0,%1,%2,%3};" \
        : "+f"((c)[0]), "+f"((c)[1]), "+f"((c)[2]), "+f"((c)[3]) \
        : "r"(a0), "r"(a1), "r"(a2), "r"(a3), "r"(b0), "r"(b1))

#define CP_ASYNC16(dst, src) \
    asm volatile("cp.async.ca.shared.global [%0], [%1], 16;" \
                 :: "r"((uint32_t)(dst)), "l"(src))
#define CP_ASYNC_COMMIT() asm volatile("cp.async.commit_group;" ::: "memory")
#define CP_ASYNC_WAIT0()  asm volatile("cp.async.wait_group 0;" ::: "memory")

// ---------------------------------------------------------------------------
// fp16 2-level split, 3 product terms:
//   X chunks: [hi, hi, mid]   C chunks: [hi, mid, hi]
//   sum = hi_x*hi_c + hi_x*mid_c + mid_x*hi_c  (drop mid*mid ~ 2^-22)
// ---------------------------------------------------------------------------
__device__ __forceinline__ void split2h(float v, __half& h, __half& m) {
    h = __float2half_rn(v);
    m = __float2half_rn(v - __half2float(h));
}
__device__ __forceinline__ uint32_t hpack(__half a, __half b) {
    __half2 t = __halves2half2(a, b);
    return *reinterpret_cast<uint32_t*>(&t);
}

// ---------------------------------------------------------------------------
// Kernel 1: norms + scratch init + fp16 split. 16 threads per row (one per
// float4 quad), coalesced reads and chunk writes, 16-lane shuffle for norms.
// ---------------------------------------------------------------------------
__global__ void vq_prep_split(const float* __restrict__ x,
                              const float* __restrict__ cb) {
    int t = blockIdx.x * blockDim.x + threadIdx.x;  // (N_ROWS+KCODES)*16 threads
    if (t == 0) g_done = 0;
    int rowg = t >> 4, q = t & 15;
    const bool isx = rowg < N_ROWS;
    const int row = isx ? rowg : rowg - N_ROWS;
    float4 v = reinterpret_cast<const float4*>(isx ? x : cb)[(size_t)row * 16 + q];

    float s = v.x * v.x + v.y * v.y + v.z * v.z + v.w * v.w;
#pragma unroll
    for (int off = 1; off <= 8; off <<= 1)
        s += __shfl_xor_sync(0xFFFFFFFFu, s, off);

    __half h[4], m[4];
    split2h(v.x, h[0], m[0]);
    split2h(v.y, h[1], m[1]);
    split2h(v.z, h[2], m[2]);
    split2h(v.w, h[3], m[3]);
    uint2 hh = make_uint2(hpack(h[0], h[1]), hpack(h[2], h[3]));
    uint2 mm = make_uint2(hpack(m[0], m[1]), hpack(m[2], m[3]));
    size_t base = (size_t)row * KAUG + q * 4;
    if (isx) {
        *reinterpret_cast<uint2*>(&g_xaug[base + 0 * 64]) = hh;
        *reinterpret_cast<uint2*>(&g_xaug[base + 1 * 64]) = hh;
        *reinterpret_cast<uint2*>(&g_xaug[base + 2 * 64]) = mm;
        if (q == 0) {
            g_xnorm[row] = s;
            g_rowbest[row] = 0xFFFFFFFFFFFFFFFFull;
        }
    } else {
        *reinterpret_cast<uint2*>(&g_caug[base + 0 * 64]) = hh;
        *reinterpret_cast<uint2*>(&g_caug[base + 1 * 64]) = mm;
        *reinterpret_cast<uint2*>(&g_caug[base + 2 * 64]) = hh;
        if (q == 0) {
            g_cnorm[row] = s;
            g_colmin[row] = 0x7F800000u;
        }
    }
}

// ---------------------------------------------------------------------------
// Kernel 2: mma.sync HMMA GEMM (128x128 tile, K=192), CTILES c-tiles per CTA
// with A staged once. 16 warps in a 4x4 grid; warp tile 32x32.
// ---------------------------------------------------------------------------
__global__ void __launch_bounds__(NT, 2) vq_main_mma() {
    extern __shared__ char smem[];
    uint32_t sb = smem_to_u32(smem);
    float* cn_s = reinterpret_cast<float*>(smem + SO_CN);
    float* xn_s = reinterpret_cast<float*>(smem + SO_XN);
    unsigned long long* rowred =
        reinterpret_cast<unsigned long long*>(smem + SO_ROWRED);
    unsigned int* colred = reinterpret_cast<unsigned int*>(smem + SO_COLRED);

    const int tid = threadIdx.x;
    const int wid = tid >> 5, lane = tid & 31;
    const int wm = wid & 3;       // m block of 32
    const int wn = wid >> 2;      // n block of 32
    const int m0 = blockIdx.x * M_TILE;
    const int c0base = blockIdx.y * (CTILES * N_TILE);

    // Stage A tile once (128 x 192 halfs) via cp.async.
    const uint4* xa = reinterpret_cast<const uint4*>(g_xaug);  // 24 uint4 / row
    const uint4* ca = reinterpret_cast<const uint4*>(g_caug);
#pragma unroll
    for (int i = 0; i < 6; i++) {
        int idx = tid + i * NT;             // 0..3071
        int r = idx / 24, q = idx - r * 24;
        CP_ASYNC16(sb + SO_A + r * ROWB + q * 16, &xa[(size_t)(m0 + r) * 24 + q]);
    }
    if (tid < 128) {
        xn_s[tid] = g_xnorm[m0 + tid];
        rowred[tid] = 0xFFFFFFFFFFFFFFFFull;
    }

    // ldmatrix bases (tile-independent)
    uint32_t a_base = sb + SO_A + (wm * 32 + (lane & 15)) * ROWB + (lane >> 4) * 16;
    const int bg = lane >> 3;
    const int bn = ((bg >> 1) << 3) + (lane & 7);
    const int bk = (bg & 1) * 16;
    uint32_t b_base0 = sb + SO_B + (wn * 32 + 0 + bn) * ROWB + bk;
    uint32_t b_base1 = sb + SO_B + (wn * 32 + 16 + bn) * ROWB + bk;

    const int qr = lane >> 2, qc = lane & 3;
    const float INF = __int_as_float(0x7f800000);

    for (int ti = 0; ti < CTILES; ti++) {
        const int c0 = c0base + ti * N_TILE;

        // Stage B tile for this c-tile.
#pragma unroll
        for (int i = 0; i < 6; i++) {
            int idx = tid + i * NT;
            int r = idx / 24, q = idx - r * 24;
            CP_ASYNC16(sb + SO_B + r * ROWB + q * 16,
                       &ca[(size_t)(c0 + r) * 24 + q]);
        }
        CP_ASYNC_COMMIT();
        if (tid < 128) {
            cn_s[tid] = g_cnorm[c0 + tid];
            colred[tid] = 0x7F800000u;
        }
        CP_ASYNC_WAIT0();
        __syncthreads();

        float acc[2][4][4];
#pragma unroll
        for (int mi = 0; mi < 2; mi++)
#pragma unroll
            for (int ni = 0; ni < 4; ni++)
#pragma unroll
                for (int j = 0; j < 4; j++) acc[mi][ni][j] = 0.f;

#pragma unroll
        for (int ks = 0; ks < KSTEPS; ks++) {
            uint32_t a[2][4], b[2][4];
#pragma unroll
            for (int mi = 0; mi < 2; mi++)
                LDSM_X4(a[mi][0], a[mi][1], a[mi][2], a[mi][3],
                        a_base + mi * 16 * ROWB + ks * 32);
            LDSM_X4(b[0][0], b[0][1], b[0][2], b[0][3], b_base0 + ks * 32);
            LDSM_X4(b[1][0], b[1][1], b[1][2], b[1][3], b_base1 + ks * 32);
#pragma unroll
            for (int mi = 0; mi < 2; mi++) {
#pragma unroll
                for (int ni = 0; ni < 4; ni++) {
                    const int p = ni >> 1, o = (ni & 1) * 2;
                    MMA16816(acc[mi][ni], a[mi][0], a[mi][1], a[mi][2], a[mi][3],
                             b[p][o], b[p][o + 1]);
                }
            }
        }

        // ---------------- Epilogue for this c-tile ----------------
        float cmin[4][2];
#pragma unroll
        for (int ni = 0; ni < 4; ni++) { cmin[ni][0] = INF; cmin[ni][1] = INF; }

#pragma unroll
        for (int mi = 0; mi < 2; mi++) {
#pragma unroll
            for (int h = 0; h < 2; h++) {
                int row_l = wm * 32 + mi * 16 + qr + 8 * h;
                float xn = xn_s[row_l];
                float bd = INF;
                int bc = 0;
#pragma unroll
                for (int ni = 0; ni < 4; ni++) {
#pragma unroll
                    for (int c = 0; c < 2; c++) {
                        int col_l = wn * 32 + ni * 8 + 2 * qc + c;
                        float d = fmaf(-2.f, acc[mi][ni][2 * h + c],
                                       xn + cn_s[col_l]);
                        if (d < bd) { bd = d; bc = col_l; }
                        cmin[ni][c] = fminf(cmin[ni][c], d);
                    }
                }
                unsigned long long u =
                    ((unsigned long long)__float_as_uint(bd) << 32) |
                    (unsigned int)(c0 + bc);
#pragma unroll
                for (int off = 1; off <= 2; off <<= 1) {
                    unsigned long long o = __shfl_xor_sync(0xFFFFFFFFu, u, off);
                    if (o < u) u = o;
                }
                if (qc == 0) atomicMin(&rowred[row_l], u);
            }
        }
#pragma unroll
        for (int ni = 0; ni < 4; ni++) {
#pragma unroll
            for (int c = 0; c < 2; c++) {
                float v = cmin[ni][c];
#pragma unroll
                for (int off = 4; off <= 16; off <<= 1)
                    v = fminf(v, __shfl_xor_sync(0xFFFFFFFFu, v, off));
                if (qr == 0) {
                    int col_l = wn * 32 + ni * 8 + 2 * qc + c;
                    atomicMin(&colred[col_l], __float_as_uint(v));
                }
            }
        }
        __syncthreads();
        if (tid < 128) atomicMin(&g_colmin[c0 + tid], colred[tid]);
        __syncthreads();   // protect B tile + colred before restage / exit
    }

    if (tid < 128) atomicMin(&g_rowbest[m0 + tid], rowred[tid]);
}

// ---------------------------------------------------------------------------
// Kernel 3 (fused): gather emb, write out = x + (emb-x), partial SSE;
// last block finalizes the loss scalar (deterministic fixed-order sums).
// ---------------------------------------------------------------------------
__global__ void vq_gather_final(const float* __restrict__ x,
                                const float* __restrict__ cb,
                                float* __restrict__ out, int nd, int out_size) {
    int row = blockIdx.x * blockDim.x + threadIdx.x;
    int tok = (int)(unsigned int)(g_rowbest[row] & 0xFFFFFFFFull);
    const float4* xg = reinterpret_cast<const float4*>(x) + (size_t)row * 16;
    const float4* cg = reinterpret_cast<const float4*>(cb) + (size_t)tok * 16;
    float4* og = reinterpret_cast<float4*>(out) + (size_t)row * 16;
    float s = 0.f;
#pragma unroll
    for (int i = 0; i < 16; i++) {
        float4 xv = xg[i];
        float4 e = cg[i];
        float dx = e.x - xv.x, dy = e.y - xv.y, dz = e.z - xv.z, dw = e.w - xv.w;
        s += dx * dx + dy * dy + dz * dz + dw * dw;
        og[i] = make_float4(xv.x + dx, xv.y + dy, xv.z + dz, xv.w + dw);
    }
#pragma unroll
    for (int off = 16; off; off >>= 1) s += __shfl_xor_sync(0xFFFFFFFFu, s, off);
    __shared__ float red[8];
    __shared__ unsigned int ticket;
    int lane = threadIdx.x & 31, wid = threadIdx.x >> 5;
    if (lane == 0) red[wid] = s;
    __syncthreads();
    if (threadIdx.x == 0) {
        float t = 0.f;
#pragma unroll
        for (int i = 0; i < 8; i++) t += red[i];
        g_partials[blockIdx.x] = t;
        __threadfence();
        ticket = atomicAdd(&g_done, 1u);
    }
    __syncthreads();
    if (ticket != gridDim.x - 1) return;

    // Last block: finalize the loss (256 threads)
    int t = threadIdx.x;
    float ps = (t < (N_ROWS / 256)) ? g_partials[t] : 0.f;
    float cm = 0.f;
#pragma unroll
    for (int i = 0; i < KCODES / 256; i++)
        cm += __uint_as_float(g_colmin[t + i * 256]);
#pragma unroll
    for (int off = 16; off; off >>= 1) {
        ps += __shfl_xor_sync(0xFFFFFFFFu, ps, off);
        cm += __shfl_xor_sync(0xFFFFFFFFu, cm, off);
    }
    __shared__ float sh_s[8], sh_c[8];
    if (lane == 0) { sh_s[wid] = ps; sh_c[wid] = cm; }
    __syncthreads();
    if (t == 0) {
        float st = 0.f, ct = 0.f;
#pragma unroll
        for (int i = 0; i < 8; i++) { st += sh_s[i]; ct += sh_c[i]; }
        float loss = 1.25f * (st / (float)nd) + 0.1f * (ct * (1.f / (float)KCODES));
        for (int i = nd; i < out_size; i++) out[i] = loss;
    }
}

// ---------------------------------------------------------------------------
extern "C" void kernel_launch(void* const* d_in, const int* in_sizes, int n_in,
                              void* d_out, int out_size) {
    const float* x = (const float*)d_in[0];   // [32,32,32,64] fp32
    const float* cb = (const float*)d_in[1];  // [1024,64] fp32
    float* out = (float*)d_out;
    int nd = in_sizes[0];  // 2097152

    cudaFuncSetAttribute(vq_main_mma, cudaFuncAttributeMaxDynamicSharedMemorySize,
                         SMEM_SZ);

    vq_prep_split<<<((N_ROWS + KCODES) * 16) / 256, 256>>>(x, cb);
    dim3 grid(N_ROWS / M_TILE, KCODES / (CTILES * N_TILE));  // (256, 4)
    vq_main_mma<<<grid, NT, SMEM_SZ>>>();
    vq_gather_final<<<N_ROWS / 256, 256>>>(x, cb, out, nd, out_size);
}

// round 16
// speedup vs baseline: 2.0170x; 1.1694x over previous
#include <cuda_runtime.h>
#include <cuda_fp16.h>
#include <cstdint>

// Problem constants (B,H,W,D = 32,32,32,64; K = 1024)
#define N_ROWS 32768
#define DIM    64
#define KCODES 1024
#define M_TILE 128
#define N_TILE 128
#define CTILES 2                // c-tiles per CTA (A staged once)
#define KAUG   192              // GMEM: 3 chunks x 64 (fp16 2-level split), 384 B rows
#define NT     512              // threads per CTA in main kernel (16 warps, 4x4)

// ---------------------------------------------------------------------------
// Device scratch (no allocation allowed)
// ---------------------------------------------------------------------------
__device__ unsigned long long g_rowbest[N_ROWS];   // (dist_bits<<32)|code
__device__ unsigned int       g_colmin[KCODES];    // per-code min dist (float bits)
__device__ float              g_xnorm[N_ROWS];
__device__ float              g_cnorm[KCODES];
__device__ float              g_partials[N_ROWS / 256];
__device__ unsigned int       g_done;
__device__ __align__(16) __half g_xaug[(size_t)N_ROWS * KAUG];  // 12.6 MB, 384 B rows
__device__ __align__(16) __half g_caug[(size_t)KCODES * KAUG];  // 384 KB

// ---------------------------------------------------------------------------
// SMEM layout (dynamic). Deduped rows: 128 unique halfs [hi64|mid64] = 256 B
// data + 16 B pad = 272 B stride (68 words ≡ 4 banks mod 32 => identical
// conflict-free ldmatrix rotation as the 400 B layout).
// ---------------------------------------------------------------------------
#define ROWB      272
#define SO_CN     0                        // 128 floats
#define SO_XN     512                      // 128 floats
#define SO_ROWRED 1024                     // 128 u64
#define SO_COLRED 2048                     // 128 u32
#define SO_A      2560                     // 128 * 272 B = 34816
#define SO_B      (SO_A + M_TILE * ROWB)   // 37376
#define SMEM_SZ   (SO_B + N_TILE * ROWB)   // 72192 B

__device__ __forceinline__ uint32_t smem_to_u32(const void* p) {
    uint32_t a;
    asm("{ .reg .u64 t; cvta.to.shared.u64 t, %1; cvt.u32.u64 %0, t; }"
        : "=r"(a) : "l"(p));
    return a;
}

#define LDSM_X4(r0, r1, r2, r3, addr) \
    asm volatile("ldmatrix.sync.aligned.m8n8.x4.shared.b16 {%0,%1,%2,%3}, [%4];" \
                 : "=r"(r0), "=r"(r1), "=r"(r2), "=r"(r3) : "r"(addr))

#define MMA16816(c, a0, a1, a2, a3, b0, b1) \
    asm volatile( \
        "mma.sync.aligned.m16n8k16.row.col.f32.f16.f16.f32 " \
        "{%0,%1,%2,%3}, {%4,%5,%6,%7}, {%8,%9}, {%0,%1,%2,%3};" \
        : "+f"((c)[0]), "+f"((c)[1]), "+f"((c)[2]), "+f"((c)[3]) \
        : "r"(a0), "r"(a1), "r"(a2), "r"(a3), "r"(b0), "r"(b1))

#define CP_ASYNC16(dst, src) \
    asm volatile("cp.async.ca.shared.global [%0], [%1], 16;" \
                 :: "r"((uint32_t)(dst)), "l"(src))
#define CP_ASYNC_COMMIT() asm volatile("cp.async.commit_group;" ::: "memory")
#define CP_ASYNC_WAIT0()  asm volatile("cp.async.wait_group 0;" ::: "memory")

// ---------------------------------------------------------------------------
// fp16 2-level split, 3 product terms:
//   GMEM X chunks: [hi, hi, mid]   GMEM C chunks: [hi, mid, hi]
//   sum = hi_x*hi_c + hi_x*mid_c + mid_x*hi_c  (drop mid*mid ~ 2^-22)
// SMEM stores the unique pair [hi | mid] per row; the k-loop revisits regions.
// ---------------------------------------------------------------------------
__device__ __forceinline__ void split2h(float v, __half& h, __half& m) {
    h = __float2half_rn(v);
    m = __float2half_rn(v - __half2float(h));
}
__device__ __forceinline__ uint32_t hpack(__half a, __half b) {
    __half2 t = __halves2half2(a, b);
    return *reinterpret_cast<uint32_t*>(&t);
}

// ---------------------------------------------------------------------------
// Kernel 1: norms + scratch init + fp16 split. 16 threads per row (one per
// float4 quad), coalesced reads and chunk writes, 16-lane shuffle for norms.
// (Unchanged from the 72.4 us round — known good.)
// ---------------------------------------------------------------------------
__global__ void vq_prep_split(const float* __restrict__ x,
                              const float* __restrict__ cb) {
    int t = blockIdx.x * blockDim.x + threadIdx.x;  // (N_ROWS+KCODES)*16 threads
    if (t == 0) g_done = 0;
    int rowg = t >> 4, q = t & 15;
    const bool isx = rowg < N_ROWS;
    const int row = isx ? rowg : rowg - N_ROWS;
    float4 v = reinterpret_cast<const float4*>(isx ? x : cb)[(size_t)row * 16 + q];

    float s = v.x * v.x + v.y * v.y + v.z * v.z + v.w * v.w;
#pragma unroll
    for (int off = 1; off <= 8; off <<= 1)
        s += __shfl_xor_sync(0xFFFFFFFFu, s, off);

    __half h[4], m[4];
    split2h(v.x, h[0], m[0]);
    split2h(v.y, h[1], m[1]);
    split2h(v.z, h[2], m[2]);
    split2h(v.w, h[3], m[3]);
    uint2 hh = make_uint2(hpack(h[0], h[1]), hpack(h[2], h[3]));
    uint2 mm = make_uint2(hpack(m[0], m[1]), hpack(m[2], m[3]));
    size_t base = (size_t)row * KAUG + q * 4;
    if (isx) {
        *reinterpret_cast<uint2*>(&g_xaug[base + 0 * 64]) = hh;
        *reinterpret_cast<uint2*>(&g_xaug[base + 1 * 64]) = hh;
        *reinterpret_cast<uint2*>(&g_xaug[base + 2 * 64]) = mm;
        if (q == 0) {
            g_xnorm[row] = s;
            g_rowbest[row] = 0xFFFFFFFFFFFFFFFFull;
        }
    } else {
        *reinterpret_cast<uint2*>(&g_caug[base + 0 * 64]) = hh;
        *reinterpret_cast<uint2*>(&g_caug[base + 1 * 64]) = mm;
        *reinterpret_cast<uint2*>(&g_caug[base + 2 * 64]) = hh;
        if (q == 0) {
            g_cnorm[row] = s;
            g_colmin[row] = 0x7F800000u;
        }
    }
}

// ---------------------------------------------------------------------------
// Kernel 2: mma.sync HMMA GEMM (128x128 tile, logical K=192 from 128 stored
// halfs/row). CTILES c-tiles per CTA with A staged once. 16 warps (4x4),
// warp tile 32x32. j-grouped k-loop: per 16-k slice load A_hi/A_mid/B_hi/B_mid
// once (8 LDSM) and fire all 3 term groups (24 MMA).
// ---------------------------------------------------------------------------
__global__ void __launch_bounds__(NT, 2) vq_main_mma() {
    extern __shared__ char smem[];
    uint32_t sb = smem_to_u32(smem);
    float* cn_s = reinterpret_cast<float*>(smem + SO_CN);
    float* xn_s = reinterpret_cast<float*>(smem + SO_XN);
    unsigned long long* rowred =
        reinterpret_cast<unsigned long long*>(smem + SO_ROWRED);
    unsigned int* colred = reinterpret_cast<unsigned int*>(smem + SO_COLRED);

    const int tid = threadIdx.x;
    const int wid = tid >> 5, lane = tid & 31;
    const int wm = wid & 3;       // m block of 32
    const int wn = wid >> 2;      // n block of 32
    const int m0 = blockIdx.x * M_TILE;
    const int c0base = blockIdx.y * (CTILES * N_TILE);

    // Stage A tile once: unique chunks {0,2} of each 384 B GMEM row ->
    // smem row [hi | mid] (256 B data, 272 B stride).
    const uint4* xa = reinterpret_cast<const uint4*>(g_xaug);  // 24 uint4 / row
    const uint4* ca = reinterpret_cast<const uint4*>(g_caug);
#pragma unroll
    for (int i = 0; i < 4; i++) {
        int idx = tid + i * NT;             // 0..2047
        int r = idx >> 4, qd = idx & 15;
        int qg = (qd < 8) ? qd : qd + 8;    // skip duplicate chunk 1 (hi)
        CP_ASYNC16(sb + SO_A + r * ROWB + qd * 16,
                   &xa[(size_t)(m0 + r) * 24 + qg]);
    }
    if (tid < 128) {
        xn_s[tid] = g_xnorm[m0 + tid];
        rowred[tid] = 0xFFFFFFFFFFFFFFFFull;
    }

    // ldmatrix bases (tile-independent)
    uint32_t a_base = sb + SO_A + (wm * 32 + (lane & 15)) * ROWB + (lane >> 4) * 16;
    const int bg = lane >> 3;
    const int bn = ((bg >> 1) << 3) + (lane & 7);
    const int bk = (bg & 1) * 16;
    uint32_t b_base0 = sb + SO_B + (wn * 32 + 0 + bn) * ROWB + bk;
    uint32_t b_base1 = sb + SO_B + (wn * 32 + 16 + bn) * ROWB + bk;

    const int qr = lane >> 2, qc = lane & 3;
    const float INF = __int_as_float(0x7f800000);

    for (int ti = 0; ti < CTILES; ti++) {
        const int c0 = c0base + ti * N_TILE;

        // Stage B tile: unique chunks {0,1} ([hi | mid]) are the first 256 B
        // of each 384 B GMEM row -> contiguous copy.
#pragma unroll
        for (int i = 0; i < 4; i++) {
            int idx = tid + i * NT;
            int r = idx >> 4, qd = idx & 15;
            CP_ASYNC16(sb + SO_B + r * ROWB + qd * 16,
                       &ca[(size_t)(c0 + r) * 24 + qd]);
        }
        CP_ASYNC_COMMIT();
        if (tid < 128) {
            cn_s[tid] = g_cnorm[c0 + tid];
            colred[tid] = 0x7F800000u;
        }
        CP_ASYNC_WAIT0();
        __syncthreads();

        float acc[2][4][4];
#pragma unroll
        for (int mi = 0; mi < 2; mi++)
#pragma unroll
            for (int ni = 0; ni < 4; ni++)
#pragma unroll
                for (int j = 0; j < 4; j++) acc[mi][ni][j] = 0.f;

#pragma unroll
        for (int j = 0; j < 4; j++) {
            const int oh = j * 32;          // hi region byte offset
            const int om = 128 + j * 32;    // mid region byte offset
            uint32_t ah[2][4], am[2][4], bh[2][4], bm[2][4];
#pragma unroll
            for (int mi = 0; mi < 2; mi++) {
                LDSM_X4(ah[mi][0], ah[mi][1], ah[mi][2], ah[mi][3],
                        a_base + mi * 16 * ROWB + oh);
                LDSM_X4(am[mi][0], am[mi][1], am[mi][2], am[mi][3],
                        a_base + mi * 16 * ROWB + om);
            }
            LDSM_X4(bh[0][0], bh[0][1], bh[0][2], bh[0][3], b_base0 + oh);
            LDSM_X4(bh[1][0], bh[1][1], bh[1][2], bh[1][3], b_base1 + oh);
            LDSM_X4(bm[0][0], bm[0][1], bm[0][2], bm[0][3], b_base0 + om);
            LDSM_X4(bm[1][0], bm[1][1], bm[1][2], bm[1][3], b_base1 + om);
#pragma unroll
            for (int mi = 0; mi < 2; mi++) {
#pragma unroll
                for (int ni = 0; ni < 4; ni++) {
                    const int p = ni >> 1, o = (ni & 1) * 2;
                    MMA16816(acc[mi][ni], ah[mi][0], ah[mi][1], ah[mi][2],
                             ah[mi][3], bh[p][o], bh[p][o + 1]);
                }
            }
#pragma unroll
            for (int mi = 0; mi < 2; mi++) {
#pragma unroll
                for (int ni = 0; ni < 4; ni++) {
                    const int p = ni >> 1, o = (ni & 1) * 2;
                    MMA16816(acc[mi][ni], ah[mi][0], ah[mi][1], ah[mi][2],
                             ah[mi][3], bm[p][o], bm[p][o + 1]);
                }
            }
#pragma unroll
            for (int mi = 0; mi < 2; mi++) {
#pragma unroll
                for (int ni = 0; ni < 4; ni++) {
                    const int p = ni >> 1, o = (ni & 1) * 2;
                    MMA16816(acc[mi][ni], am[mi][0], am[mi][1], am[mi][2],
                             am[mi][3], bh[p][o], bh[p][o + 1]);
                }
            }
        }

        // ---------------- Epilogue for this c-tile ----------------
        float cmin[4][2];
#pragma unroll
        for (int ni = 0; ni < 4; ni++) { cmin[ni][0] = INF; cmin[ni][1] = INF; }

#pragma unroll
        for (int mi = 0; mi < 2; mi++) {
#pragma unroll
            for (int h = 0; h < 2; h++) {
                int row_l = wm * 32 + mi * 16 + qr + 8 * h;
                float xn = xn_s[row_l];
                float bd = INF;
                int bc = 0;
#pragma unroll
                for (int ni = 0; ni < 4; ni++) {
#pragma unroll
                    for (int c = 0; c < 2; c++) {
                        int col_l = wn * 32 + ni * 8 + 2 * qc + c;
                        float d = fmaf(-2.f, acc[mi][ni][2 * h + c],
                                       xn + cn_s[col_l]);
                        if (d < bd) { bd = d; bc = col_l; }
                        cmin[ni][c] = fminf(cmin[ni][c], d);
                    }
                }
                unsigned long long u =
                    ((unsigned long long)__float_as_uint(bd) << 32) |
                    (unsigned int)(c0 + bc);
#pragma unroll
                for (int off = 1; off <= 2; off <<= 1) {
                    unsigned long long o = __shfl_xor_sync(0xFFFFFFFFu, u, off);
                    if (o < u) u = o;
                }
                if (qc == 0) atomicMin(&rowred[row_l], u);
            }
        }
#pragma unroll
        for (int ni = 0; ni < 4; ni++) {
#pragma unroll
            for (int c = 0; c < 2; c++) {
                float v = cmin[ni][c];
#pragma unroll
                for (int off = 4; off <= 16; off <<= 1)
                    v = fminf(v, __shfl_xor_sync(0xFFFFFFFFu, v, off));
                if (qr == 0) {
                    int col_l = wn * 32 + ni * 8 + 2 * qc + c;
                    atomicMin(&colred[col_l], __float_as_uint(v));
                }
            }
        }
        __syncthreads();
        if (tid < 128) atomicMin(&g_colmin[c0 + tid], colred[tid]);
        __syncthreads();   // protect B tile + colred before restage / exit
    }

    if (tid < 128) atomicMin(&g_rowbest[m0 + tid], rowred[tid]);
}

// ---------------------------------------------------------------------------
// Kernel 3 (fused): gather emb, write out = x + (emb-x), partial SSE;
// last block finalizes the loss scalar (deterministic fixed-order sums).
// ---------------------------------------------------------------------------
__global__ void vq_gather_final(const float* __restrict__ x,
                                const float* __restrict__ cb,
                                float* __restrict__ out, int nd, int out_size) {
    int row = blockIdx.x * blockDim.x + threadIdx.x;
    int tok = (int)(unsigned int)(g_rowbest[row] & 0xFFFFFFFFull);
    const float4* xg = reinterpret_cast<const float4*>(x) + (size_t)row * 16;
    const float4* cg = reinterpret_cast<const float4*>(cb) + (size_t)tok * 16;
    float4* og = reinterpret_cast<float4*>(out) + (size_t)row * 16;
    float s = 0.f;
#pragma unroll
    for (int i = 0; i < 16; i++) {
        float4 xv = xg[i];
        float4 e = cg[i];
        float dx = e.x - xv.x, dy = e.y - xv.y, dz = e.z - xv.z, dw = e.w - xv.w;
        s += dx * dx + dy * dy + dz * dz + dw * dw;
        og[i] = make_float4(xv.x + dx, xv.y + dy, xv.z + dz, xv.w + dw);
    }
#pragma unroll
    for (int off = 16; off; off >>= 1) s += __shfl_xor_sync(0xFFFFFFFFu, s, off);
    __shared__ float red[8];
    __shared__ unsigned int ticket;
    int lane = threadIdx.x & 31, wid = threadIdx.x >> 5;
    if (lane == 0) red[wid] = s;
    __syncthreads();
    if (threadIdx.x == 0) {
        float t = 0.f;
#pragma unroll
        for (int i = 0; i < 8; i++) t += red[i];
        g_partials[blockIdx.x] = t;
        __threadfence();
        ticket = atomicAdd(&g_done, 1u);
    }
    __syncthreads();
    if (ticket != gridDim.x - 1) return;

    // Last block: finalize the loss (256 threads)
    int t = threadIdx.x;
    float ps = (t < (N_ROWS / 256)) ? g_partials[t] : 0.f;
    float cm = 0.f;
#pragma unroll
    for (int i = 0; i < KCODES / 256; i++)
        cm += __uint_as_float(g_colmin[t + i * 256]);
#pragma unroll
    for (int off = 16; off; off >>= 1) {
        ps += __shfl_xor_sync(0xFFFFFFFFu, ps, off);
        cm += __shfl_xor_sync(0xFFFFFFFFu, cm, off);
    }
    __shared__ float sh_s[8], sh_c[8];
    if (lane == 0) { sh_s[wid] = ps; sh_c[wid] = cm; }
    __syncthreads();
    if (t == 0) {
        float st = 0.f, ct = 0.f;
#pragma unroll
        for (int i = 0; i < 8; i++) { st += sh_s[i]; ct += sh_c[i]; }
        float loss = 1.25f * (st / (float)nd) + 0.1f * (ct * (1.f / (float)KCODES));
        for (int i = nd; i < out_size; i++) out[i] = loss;
    }
}

// ---------------------------------------------------------------------------
extern "C" void kernel_launch(void* const* d_in, const int* in_sizes, int n_in,
                              void* d_out, int out_size) {
    const float* x = (const float*)d_in[0];   // [32,32,32,64] fp32
    const float* cb = (const float*)d_in[1];  // [1024,64] fp32
    float* out = (float*)d_out;
    int nd = in_sizes[0];  // 2097152

    cudaFuncSetAttribute(vq_main_mma, cudaFuncAttributeMaxDynamicSharedMemorySize,
                         SMEM_SZ);

    vq_prep_split<<<((N_ROWS + KCODES) * 16) / 256, 256>>>(x, cb);
    dim3 grid(N_ROWS / M_TILE, KCODES / (CTILES * N_TILE));  // (256, 4)
    vq_main_mma<<<grid, NT, SMEM_SZ>>>();
    vq_gather_final<<<N_ROWS / 256, 256>>>(x, cb, out, nd, out_size);
}